// round 3
// baseline (speedup 1.0000x reference)
#include <cuda_runtime.h>
#include <math.h>
#include <stdint.h>

#define Bq   8
#define Tq   500
#define Uq   120
#define UP1  121
#define Vq   128
#define Hq   320
#define G4   1280
#define DIN  80
#define VM1  127

// ---------------- static device scratch (no runtime allocation) ----------------
__device__ float g_xp0[Bq * Tq * G4];
__device__ float g_h0 [Bq * Tq * Hq];
__device__ float g_xp1[Bq * Tq * G4];
__device__ float g_h1 [Bq * Tq * Hq];
__device__ float g_enc[Bq * Tq * Vq];
__device__ float g_xpd[Bq * UP1 * G4];
__device__ float g_hd [Bq * UP1 * Hq];
__device__ float g_dec[Bq * UP1 * Vq];
__device__ float g_lb [Bq * Tq * UP1];
__device__ float g_ly [Bq * Tq * Uq];
__device__ float g_nll[Bq];

// ---------------- generic tiled GEMM: C[M,N] = A[M,K] @ B[N,K]^T + b1 + b2 ----------------
#define GBM 128
#define GBN 64
#define GBK 16

__global__ void __launch_bounds__(256) gemm_nt(const float* __restrict__ A,
                                               const float* __restrict__ Bm,
                                               const float* __restrict__ b1,
                                               const float* __restrict__ b2,
                                               float* __restrict__ C,
                                               int M, int N, int K)
{
    __shared__ float As[GBK][GBM + 1];
    __shared__ float Bs[GBK][GBN + 1];
    int tid = threadIdx.x;
    int bm = blockIdx.y * GBM;
    int bn = blockIdx.x * GBN;
    int tx = tid & 15, ty = tid >> 4;

    float acc[8][4];
#pragma unroll
    for (int i = 0; i < 8; i++)
#pragma unroll
        for (int j = 0; j < 4; j++) acc[i][j] = 0.f;

    for (int k0 = 0; k0 < K; k0 += GBK) {
#pragma unroll
        for (int l = 0; l < 8; l++) {
            int idx = l * 256 + tid;
            int am = idx >> 4, ak = idx & 15;
            float v = 0.f;
            if (bm + am < M && k0 + ak < K) v = A[(size_t)(bm + am) * K + k0 + ak];
            As[ak][am] = v;
        }
#pragma unroll
        for (int l = 0; l < 4; l++) {
            int idx = l * 256 + tid;
            int bnn = idx >> 4, bk = idx & 15;
            float v = 0.f;
            if (bn + bnn < N && k0 + bk < K) v = Bm[(size_t)(bn + bnn) * K + k0 + bk];
            Bs[bk][bnn] = v;
        }
        __syncthreads();
#pragma unroll
        for (int k = 0; k < GBK; k++) {
            float af[8], bf[4];
#pragma unroll
            for (int i = 0; i < 8; i++) af[i] = As[k][ty + 16 * i];
#pragma unroll
            for (int j = 0; j < 4; j++) bf[j] = Bs[k][tx + 16 * j];
#pragma unroll
            for (int i = 0; i < 8; i++)
#pragma unroll
                for (int j = 0; j < 4; j++) acc[i][j] += af[i] * bf[j];
        }
        __syncthreads();
    }

#pragma unroll
    for (int j = 0; j < 4; j++) {
        int n = bn + tx + 16 * j;
        if (n >= N) continue;
        float bias = (b1 ? b1[n] : 0.f) + (b2 ? b2[n] : 0.f);
#pragma unroll
        for (int i = 0; i < 8; i++) {
            int m = bm + ty + 16 * i;
            if (m < M) C[(size_t)m * N + n] = acc[i][j] + bias;
        }
    }
}

// ---------------- LSTM: 8-CTA cluster per batch, register-resident weights ----------------
// CTA = 40 hidden units = 160 gate rows. 320 threads: lr = tid>>1 in [0,160),
// half = tid&1 covers half the K-dim (160 of 320). h broadcast via DSMEM stores.
__global__ void __cluster_dims__(8, 1, 1) __launch_bounds__(320, 1)
lstm_kernel(const float* __restrict__ Whh,     // [4H, H]
            const float* __restrict__ xproj,   // [B, T, 4H]  (biases already added)
            float* __restrict__ hout,          // [B, T, H]
            int T)
{
    __shared__ __align__(16) float hbuf[2][Hq];
    __shared__ float gbuf[160];

    unsigned rank;
    asm("mov.u32 %0, %%cluster_ctarank;" : "=r"(rank));
    int batch = blockIdx.x >> 3;

    int tid  = threadIdx.x;
    int half = tid & 1;
    int lr   = tid >> 1;        // gate row within CTA: 0..159
    int j    = lr >> 2;         // local hidden unit 0..39
    int gate = lr & 3;          // 0=i 1=f 2=g 3=o
    int unit = (int)rank * 40 + j;
    int row  = gate * Hq + unit;

    // register-resident weight slice: 160 floats
    float w[160];
    {
        const float4* W4 = reinterpret_cast<const float4*>(Whh + (size_t)row * Hq + half * 160);
#pragma unroll
        for (int i = 0; i < 40; i++) {
            float4 v = W4[i];
            w[4 * i + 0] = v.x; w[4 * i + 1] = v.y;
            w[4 * i + 2] = v.z; w[4 * i + 3] = v.w;
        }
    }

    hbuf[0][tid] = 0.f;         // blockDim.x == Hq == 320
    float c = 0.f;

    const float* xp = xproj + ((size_t)batch * T) * G4 + row;
    float xg_next = (half == 0) ? __ldg(xp) : 0.f;

    asm volatile("barrier.cluster.arrive.aligned;" ::: "memory");
    asm volatile("barrier.cluster.wait.aligned;" ::: "memory");

    for (int t = 0; t < T; t++) {
        int cur = t & 1, nxt = cur ^ 1;
        float xg = xg_next;
        if (half == 0 && t + 1 < T) xg_next = __ldg(xp + (size_t)(t + 1) * G4);

        const float4* h4 = reinterpret_cast<const float4*>(&hbuf[cur][half * 160]);
        float a0 = 0.f, a1 = 0.f, a2 = 0.f, a3 = 0.f;
#pragma unroll
        for (int i = 0; i < 40; i++) {
            float4 hv = h4[i];
            a0 += w[4 * i + 0] * hv.x;
            a1 += w[4 * i + 1] * hv.y;
            a2 += w[4 * i + 2] * hv.z;
            a3 += w[4 * i + 3] * hv.w;
        }
        float a = (a0 + a1) + (a2 + a3);

        if (half) gbuf[lr] = a;
        __syncthreads();
        if (!half) gbuf[lr] = a + gbuf[lr] + xg;
        __syncthreads();

        if (tid < 40) {
            float gi = gbuf[4 * tid + 0];
            float gf = gbuf[4 * tid + 1];
            float gg = gbuf[4 * tid + 2];
            float go = gbuf[4 * tid + 3];
            float i_ = 1.f / (1.f + expf(-gi));
            float f_ = 1.f / (1.f + expf(-gf));
            float g_ = tanhf(gg);
            float o_ = 1.f / (1.f + expf(-go));
            c = f_ * c + i_ * g_;
            float h = o_ * tanhf(c);

            int u_global = (int)rank * 40 + tid;
            hout[((size_t)batch * T + t) * Hq + u_global] = h;

            unsigned laddr = (unsigned)__cvta_generic_to_shared(&hbuf[nxt][u_global]);
#pragma unroll
            for (int r = 0; r < 8; r++) {
                unsigned raddr;
                asm volatile("mapa.shared::cluster.u32 %0, %1, %2;"
                             : "=r"(raddr) : "r"(laddr), "r"(r));
                asm volatile("st.shared::cluster.f32 [%0], %1;"
                             :: "r"(raddr), "f"(h) : "memory");
            }
        }
        asm volatile("barrier.cluster.arrive.aligned;" ::: "memory");
        asm volatile("barrier.cluster.wait.aligned;" ::: "memory");
    }
}

// ---------------- decoder xproj via embedding gather (ymat rows are one-hot) -------------
__global__ void __launch_bounds__(256) xpd_kernel(const int* __restrict__ ys,
                                                  const float* __restrict__ Wih,   // [4H, V-1]
                                                  const float* __restrict__ bih,
                                                  const float* __restrict__ bhh)
{
    int b = blockIdx.x / UP1, u = blockIdx.x % UP1;
    int id = (u == 0) ? 0 : ys[b * Uq + u - 1];
    float* dst = g_xpd + ((size_t)b * UP1 + u) * G4;
    for (int g = threadIdx.x; g < G4; g += 256) {
        float v = bih[g] + bhh[g];
        if (id > 0) v += Wih[(size_t)g * VM1 + (id - 1)];
        dst[g] = v;
    }
}

// ---------------- joint + log-softmax -> lb (blank) and ly (label) only ------------------
__global__ void __launch_bounds__(128) joint_kernel(const int* __restrict__ ys)
{
    int b = blockIdx.y;
    int t = blockIdx.x * 4 + (threadIdx.x >> 5);
    int lane = threadIdx.x & 31;

    const float* e = g_enc + ((size_t)b * Tq + t) * Vq;
    float e0 = e[lane], e1 = e[32 + lane], e2 = e[64 + lane], e3 = e[96 + lane];
    float* lbp = g_lb + ((size_t)b * Tq + t) * UP1;
    float* lyp = g_ly + ((size_t)b * Tq + t) * Uq;

    for (int u = 0; u < UP1; u++) {
        const float* d = g_dec + ((size_t)b * UP1 + u) * Vq;
        float j0 = e0 + d[lane];
        float j1 = e1 + d[32 + lane];
        float j2 = e2 + d[64 + lane];
        float j3 = e3 + d[96 + lane];

        float m = fmaxf(fmaxf(j0, j1), fmaxf(j2, j3));
#pragma unroll
        for (int dlt = 16; dlt > 0; dlt >>= 1)
            m = fmaxf(m, __shfl_xor_sync(0xffffffffu, m, dlt));
        float s = __expf(j0 - m) + __expf(j1 - m) + __expf(j2 - m) + __expf(j3 - m);
#pragma unroll
        for (int dlt = 16; dlt > 0; dlt >>= 1)
            s += __shfl_xor_sync(0xffffffffu, s, dlt);
        float logZ = m + logf(s);

        if (lane == 0) lbp[u] = j0 - logZ;       // v = 0 lives in lane 0, register j0
        if (u < Uq) {
            int lbl = ys[b * Uq + u];            // in [1, V)
            int k = lbl >> 5, src = lbl & 31;
            float jv = (k == 0) ? j0 : (k == 1) ? j1 : (k == 2) ? j2 : j3;
            jv = __shfl_sync(0xffffffffu, jv, src);
            if (lane == 0) lyp[u] = jv - logZ;
        }
    }
}

// ---------------- RNN-T alpha recursion (closed-form row update, block scans) ------------
__device__ __forceinline__ float lse2(float a, float b)
{
    float m = fmaxf(a, b);
    if (m == -INFINITY) return -INFINITY;
    return m + log1pf(expf(-fabsf(a - b)));
}

__global__ void __launch_bounds__(128) alpha_kernel(const int* __restrict__ xlen,
                                                    const int* __restrict__ ylen)
{
    __shared__ float alpha[UP1];
    __shared__ float wbuf[4];
    int b = blockIdx.x;
    int tid = threadIdx.x;
    int lane = tid & 31, warp = tid >> 5;
    int tl = xlen[b], ul = ylen[b];

    const float* lbB = g_lb + (size_t)b * Tq * UP1;
    const float* lyB = g_ly + (size_t)b * Tq * Uq;

    // row 0: alpha0 = exclusive cumsum of ly[0]
    {
        float v = (tid >= 1 && tid <= Uq) ? lyB[tid - 1] : 0.f;
#pragma unroll
        for (int d2 = 1; d2 < 32; d2 <<= 1) {
            float tt = __shfl_up_sync(0xffffffffu, v, d2);
            if (lane >= d2) v += tt;
        }
        __syncthreads();
        if (lane == 31) wbuf[warp] = v;
        __syncthreads();
        if (tid == 0) {
            float s = 0.f;
            for (int wq = 0; wq < 4; wq++) { float tmp = wbuf[wq]; wbuf[wq] = s; s += tmp; }
        }
        __syncthreads();
        v += wbuf[warp];
        if (tid < UP1) alpha[tid] = v;
        __syncthreads();
    }

    for (int t = 1; t < tl; t++) {
        const float* lyr = lyB + (size_t)t * Uq;
        const float* lbr = lbB + (size_t)(t - 1) * UP1;

        // c = exclusive cumsum of ly[t]
        float cv = (tid >= 1 && tid <= Uq) ? lyr[tid - 1] : 0.f;
#pragma unroll
        for (int d2 = 1; d2 < 32; d2 <<= 1) {
            float tt = __shfl_up_sync(0xffffffffu, cv, d2);
            if (lane >= d2) cv += tt;
        }
        __syncthreads();
        if (lane == 31) wbuf[warp] = cv;
        __syncthreads();
        if (tid == 0) {
            float s = 0.f;
            for (int wq = 0; wq < 4; wq++) { float tmp = wbuf[wq]; wbuf[wq] = s; s += tmp; }
        }
        __syncthreads();
        cv += wbuf[warp];

        // alpha = c + cumlogsumexp(alpha_prev + lb[t-1] - c)
        float x = (tid < UP1) ? (alpha[tid] + lbr[tid] - cv) : -INFINITY;
        float z = x;
#pragma unroll
        for (int d2 = 1; d2 < 32; d2 <<= 1) {
            float tt = __shfl_up_sync(0xffffffffu, z, d2);
            if (lane >= d2) z = lse2(z, tt);
        }
        __syncthreads();
        if (lane == 31) wbuf[warp] = z;
        __syncthreads();
        if (tid == 0) {
            float s = -INFINITY;
            for (int wq = 0; wq < 4; wq++) { float tmp = wbuf[wq]; wbuf[wq] = s; s = lse2(s, tmp); }
        }
        __syncthreads();
        z = lse2(z, wbuf[warp]);
        if (tid < UP1) alpha[tid] = cv + z;
        __syncthreads();
    }

    if (tid == 0)
        g_nll[b] = -(alpha[ul] + lbB[(size_t)(tl - 1) * UP1 + ul]);
}

__global__ void mean_kernel(float* __restrict__ out)
{
    float s = 0.f;
    for (int b = 0; b < Bq; b++) s += g_nll[b];
    out[0] = s / (float)Bq;
}

// ---------------- launch ----------------
extern "C" void kernel_launch(void* const* d_in, const int* in_sizes, int n_in,
                              void* d_out, int out_size)
{
    const float* xs    = (const float*)d_in[0];
    const int*   ys    = (const int*)  d_in[1];
    const int*   xlen  = (const int*)  d_in[2];
    const int*   ylen  = (const int*)  d_in[3];
    const float* eWih0 = (const float*)d_in[4];
    const float* eWhh0 = (const float*)d_in[5];
    const float* ebih0 = (const float*)d_in[6];
    const float* ebhh0 = (const float*)d_in[7];
    const float* eWih1 = (const float*)d_in[8];
    const float* eWhh1 = (const float*)d_in[9];
    const float* ebih1 = (const float*)d_in[10];
    const float* ebhh1 = (const float*)d_in[11];
    const float* eWo   = (const float*)d_in[12];
    const float* ebo   = (const float*)d_in[13];
    /* d_in[14] = embed (one-hot; folded into xpd gather) */
    const float* dWih  = (const float*)d_in[15];
    const float* dWhh  = (const float*)d_in[16];
    const float* dbih  = (const float*)d_in[17];
    const float* dbhh  = (const float*)d_in[18];
    const float* dWo   = (const float*)d_in[19];
    const float* dbo   = (const float*)d_in[20];
    float* out = (float*)d_out;

    float *xp0, *h0, *xp1, *h1, *enc, *hd, *dec;
    cudaGetSymbolAddress((void**)&xp0, g_xp0);
    cudaGetSymbolAddress((void**)&h0,  g_h0);
    cudaGetSymbolAddress((void**)&xp1, g_xp1);
    cudaGetSymbolAddress((void**)&h1,  g_h1);
    cudaGetSymbolAddress((void**)&enc, g_enc);
    cudaGetSymbolAddress((void**)&hd,  g_hd);
    cudaGetSymbolAddress((void**)&dec, g_dec);

    const int MT = Bq * Tq;      // 4000
    const int MU = Bq * UP1;     // 968

    // encoder layer 0
    gemm_nt<<<dim3((G4 + GBN - 1) / GBN, (MT + GBM - 1) / GBM), 256>>>(
        xs, eWih0, ebih0, ebhh0, xp0, MT, G4, DIN);
    lstm_kernel<<<64, 320>>>(eWhh0, xp0, h0, Tq);

    // encoder layer 1
    gemm_nt<<<dim3((G4 + GBN - 1) / GBN, (MT + GBM - 1) / GBM), 256>>>(
        h0, eWih1, ebih1, ebhh1, xp1, MT, G4, Hq);
    lstm_kernel<<<64, 320>>>(eWhh1, xp1, h1, Tq);

    // encoder output projection
    gemm_nt<<<dim3((Vq + GBN - 1) / GBN, (MT + GBM - 1) / GBM), 256>>>(
        h1, eWo, ebo, nullptr, enc, MT, Vq, Hq);

    // decoder
    float *xpd, *hdp;
    cudaGetSymbolAddress((void**)&xpd, g_xpd);
    cudaGetSymbolAddress((void**)&hdp, g_hd);
    xpd_kernel<<<Bq * UP1, 256>>>(ys, dWih, dbih, dbhh);
    lstm_kernel<<<64, 320>>>(dWhh, xpd, hdp, UP1);
    gemm_nt<<<dim3((Vq + GBN - 1) / GBN, (MU + GBM - 1) / GBM), 256>>>(
        hdp, dWo, dbo, nullptr, dec, MU, Vq, Hq);

    // joint log-softmax (lb/ly only), alpha recursion, mean
    joint_kernel<<<dim3(Tq / 4, Bq), 128>>>(ys);
    alpha_kernel<<<Bq, 128>>>(xlen, ylen);
    mean_kernel<<<1, 1>>>(out);
}

// round 4
// speedup vs baseline: 1.2549x; 1.2549x over previous
#include <cuda_runtime.h>
#include <math.h>
#include <stdint.h>

#define Bq   8
#define Tq   500
#define Uq   120
#define UP1  121
#define Vq   128
#define Hq   320
#define G4   1280
#define DIN  80
#define VM1  127

// ---------------- static device scratch ----------------
__device__ float g_xp0[Bq * Tq * G4];
__device__ float g_h0 [Bq * Tq * Hq];
__device__ float g_xp1[Bq * Tq * G4];
__device__ float g_h1 [Bq * Tq * Hq];
__device__ float g_enc[Bq * Tq * Vq];
__device__ float g_xpd[Bq * UP1 * G4];
__device__ float g_hd [Bq * UP1 * Hq];
__device__ float g_dec[Bq * UP1 * Vq];
__device__ float g_lb [Bq * Tq * UP1];
__device__ float g_ly [Bq * Tq * Uq];
__device__ float g_nll[Bq];

__device__ __forceinline__ float tanh_f(float x)
{
    float e = __expf(2.f * fabsf(x));
    float r = 1.f - 2.f / (e + 1.f);
    return copysignf(r, x);
}

// ---------------- tiled GEMM: C[M,N] = A[M,K] @ B[N,K]^T + b1 + b2 ----------------
#define GBM 128
#define GBN 64
#define GBK 16

__global__ void __launch_bounds__(256) gemm_nt(const float* __restrict__ A,
                                               const float* __restrict__ Bm,
                                               const float* __restrict__ b1,
                                               const float* __restrict__ b2,
                                               float* __restrict__ C,
                                               int M, int N, int K)
{
    __shared__ float As[GBK][GBM + 4];
    __shared__ float Bs[GBK][GBN + 4];
    int tid = threadIdx.x;
    int bm = blockIdx.y * GBM;
    int bn = blockIdx.x * GBN;
    int tx = tid & 15, ty = tid >> 4;

    float acc[8][4];
#pragma unroll
    for (int i = 0; i < 8; i++)
#pragma unroll
        for (int j = 0; j < 4; j++) acc[i][j] = 0.f;

    for (int k0 = 0; k0 < K; k0 += GBK) {
#pragma unroll
        for (int l = 0; l < 8; l++) {
            int idx = l * 256 + tid;
            int am = idx >> 4, ak = idx & 15;
            float v = 0.f;
            if (bm + am < M && k0 + ak < K) v = A[(size_t)(bm + am) * K + k0 + ak];
            As[ak][am] = v;
        }
#pragma unroll
        for (int l = 0; l < 4; l++) {
            int idx = l * 256 + tid;
            int bnn = idx >> 4, bk = idx & 15;
            float v = 0.f;
            if (bn + bnn < N && k0 + bk < K) v = Bm[(size_t)(bn + bnn) * K + k0 + bk];
            Bs[bk][bnn] = v;
        }
        __syncthreads();
#pragma unroll
        for (int k = 0; k < GBK; k++) {
            float4 a0 = *(const float4*)&As[k][ty * 8];
            float4 a1 = *(const float4*)&As[k][ty * 8 + 4];
            float4 bv = *(const float4*)&Bs[k][tx * 4];
            float af[8] = {a0.x, a0.y, a0.z, a0.w, a1.x, a1.y, a1.z, a1.w};
            float bf[4] = {bv.x, bv.y, bv.z, bv.w};
#pragma unroll
            for (int i = 0; i < 8; i++)
#pragma unroll
                for (int j = 0; j < 4; j++) acc[i][j] += af[i] * bf[j];
        }
        __syncthreads();
    }

    int n0 = bn + tx * 4;
    float bias[4];
#pragma unroll
    for (int j = 0; j < 4; j++)
        bias[j] = (b1 ? b1[n0 + j] : 0.f) + (b2 ? b2[n0 + j] : 0.f);

#pragma unroll
    for (int i = 0; i < 8; i++) {
        int m = bm + ty * 8 + i;
        if (m >= M) continue;
        float4 r;
        r.x = acc[i][0] + bias[0];
        r.y = acc[i][1] + bias[1];
        r.z = acc[i][2] + bias[2];
        r.w = acc[i][3] + bias[3];
        *(float4*)&C[(size_t)m * N + n0] = r;
    }
}

// ---------------- LSTM: 8-CTA cluster per batch, f32x2 packed FMA, shfl gate exchange ---
// grid = 64 (enc only) or 128 (clusters 0-7 enc role, 8-15 dec role).
__global__ void __cluster_dims__(8, 1, 1) __launch_bounds__(320, 1)
lstm_kernel(const float* __restrict__ Whh_e, const float* __restrict__ xp_e,
            float* __restrict__ ho_e, int T_e,
            const float* __restrict__ Whh_d, const float* __restrict__ xp_d,
            float* __restrict__ ho_d, int T_d)
{
    __shared__ __align__(16) float hbuf[2][Hq];

    unsigned rank;
    asm("mov.u32 %0, %%cluster_ctarank;" : "=r"(rank));
    int cl = blockIdx.x >> 3;
    int is_dec = (cl >= Bq);
    int batch = cl & 7;
    const float* Whh   = is_dec ? Whh_d : Whh_e;
    const float* xproj = is_dec ? xp_d  : xp_e;
    float*       hout  = is_dec ? ho_d  : ho_e;
    int          T     = is_dec ? T_d   : T_e;

    int tid  = threadIdx.x;
    int half = tid & 1;           // K-half
    int lr   = tid >> 1;          // gate row 0..159
    int gate = lr & 3;            // i,f,g,o
    int unit = (int)rank * 40 + (lr >> 2);
    int row  = gate * Hq + unit;

    // register-resident weights: 160 floats as 40x ulonglong2 (f32x2 pairs)
    ulonglong2 wv[40];
    const ulonglong2* Wp =
        reinterpret_cast<const ulonglong2*>(Whh + (size_t)row * Hq + half * 160);
#pragma unroll
    for (int i = 0; i < 40; i++) wv[i] = Wp[i];

    hbuf[0][tid] = 0.f;
    float c = 0.f;

    const float* xp = xproj + ((size_t)batch * T) * G4 + row;
    float xg_next = (half == 0) ? __ldg(xp) : 0.f;

    int lane  = tid & 31;
    int owner = ((tid & 7) == 0);
    unsigned laddr0 = (unsigned)__cvta_generic_to_shared(&hbuf[0][unit]);
    unsigned laddr1 = (unsigned)__cvta_generic_to_shared(&hbuf[1][unit]);

    asm volatile("barrier.cluster.arrive.aligned;" ::: "memory");
    asm volatile("barrier.cluster.wait.aligned;" ::: "memory");

    for (int t = 0; t < T; t++) {
        float xg = xg_next;
        if (half == 0 && t + 1 < T) xg_next = __ldg(xp + (size_t)(t + 1) * G4);

        const ulonglong2* h2 =
            reinterpret_cast<const ulonglong2*>(&hbuf[t & 1][half * 160]);
        unsigned long long acc0 = 0ULL, acc1 = 0ULL;   // packed (0.f, 0.f)
#pragma unroll
        for (int i = 0; i < 40; i++) {
            ulonglong2 hv = h2[i];
            asm("fma.rn.f32x2 %0, %1, %2, %0;" : "+l"(acc0) : "l"(wv[i].x), "l"(hv.x));
            asm("fma.rn.f32x2 %0, %1, %2, %0;" : "+l"(acc1) : "l"(wv[i].y), "l"(hv.y));
        }
        unsigned lo0, hi0, lo1, hi1;
        asm("mov.b64 {%0,%1}, %2;" : "=r"(lo0), "=r"(hi0) : "l"(acc0));
        asm("mov.b64 {%0,%1}, %2;" : "=r"(lo1), "=r"(hi1) : "l"(acc1));
        float a = (__uint_as_float(lo0) + __uint_as_float(hi0))
                + (__uint_as_float(lo1) + __uint_as_float(hi1));
        a += __shfl_xor_sync(0xffffffffu, a, 1);   // combine K-halves (adjacent lanes)
        float g = a + xg;                          // valid on even lanes

        // branch-free activation: sigmoid for i,f,o; tanh = 2*sigmoid(2x)-1 for g
        float xs = (gate == 2) ? (g + g) : g;
        float s  = 1.f / (1.f + __expf(-xs));
        float act = (gate == 2) ? (s + s - 1.f) : s;

        int base = lane & ~7;
        float vi = __shfl_sync(0xffffffffu, act, base + 0);
        float vf = __shfl_sync(0xffffffffu, act, base + 2);
        float vg = __shfl_sync(0xffffffffu, act, base + 4);
        float vo = __shfl_sync(0xffffffffu, act, base + 6);

        if (owner) {
            c = vf * c + vi * vg;
            float h = vo * tanh_f(c);
            hout[((size_t)batch * T + t) * Hq + unit] = h;
            unsigned laddr = (t & 1) ? laddr0 : laddr1;    // write hbuf[(t+1)&1]
#pragma unroll
            for (int r = 0; r < 8; r++) {
                unsigned raddr;
                asm volatile("mapa.shared::cluster.u32 %0, %1, %2;"
                             : "=r"(raddr) : "r"(laddr), "r"(r));
                asm volatile("st.shared::cluster.f32 [%0], %1;"
                             :: "r"(raddr), "f"(h) : "memory");
            }
        }
        asm volatile("barrier.cluster.arrive.aligned;" ::: "memory");
        asm volatile("barrier.cluster.wait.aligned;" ::: "memory");
    }
}

// ---------------- decoder xproj via embedding gather (one-hot rows) ----------------
__global__ void __launch_bounds__(256) xpd_kernel(const int* __restrict__ ys,
                                                  const float* __restrict__ Wih,
                                                  const float* __restrict__ bih,
                                                  const float* __restrict__ bhh)
{
    int b = blockIdx.x / UP1, u = blockIdx.x % UP1;
    int id = (u == 0) ? 0 : ys[b * Uq + u - 1];
    float* dst = g_xpd + ((size_t)b * UP1 + u) * G4;
    for (int g = threadIdx.x; g < G4; g += 256) {
        float v = bih[g] + bhh[g];
        if (id > 0) v += Wih[(size_t)g * VM1 + (id - 1)];
        dst[g] = v;
    }
}

// ---------------- joint + log-softmax -> lb (blank) and ly (label) only ----------------
__global__ void __launch_bounds__(128) joint_kernel(const int* __restrict__ ys)
{
    int b = blockIdx.y;
    int t = blockIdx.x * 4 + (threadIdx.x >> 5);
    int lane = threadIdx.x & 31;

    const float* e = g_enc + ((size_t)b * Tq + t) * Vq;
    float e0 = e[lane], e1 = e[32 + lane], e2 = e[64 + lane], e3 = e[96 + lane];
    float* lbp = g_lb + ((size_t)b * Tq + t) * UP1;
    float* lyp = g_ly + ((size_t)b * Tq + t) * Uq;

    for (int u = 0; u < UP1; u++) {
        const float* d = g_dec + ((size_t)b * UP1 + u) * Vq;
        float j0 = e0 + d[lane];
        float j1 = e1 + d[32 + lane];
        float j2 = e2 + d[64 + lane];
        float j3 = e3 + d[96 + lane];

        float m = fmaxf(fmaxf(j0, j1), fmaxf(j2, j3));
#pragma unroll
        for (int dlt = 16; dlt > 0; dlt >>= 1)
            m = fmaxf(m, __shfl_xor_sync(0xffffffffu, m, dlt));
        float s = __expf(j0 - m) + __expf(j1 - m) + __expf(j2 - m) + __expf(j3 - m);
#pragma unroll
        for (int dlt = 16; dlt > 0; dlt >>= 1)
            s += __shfl_xor_sync(0xffffffffu, s, dlt);
        float logZ = m + __logf(s);

        if (lane == 0) lbp[u] = j0 - logZ;
        if (u < Uq) {
            int lbl = ys[b * Uq + u];
            int k = lbl >> 5, src = lbl & 31;
            float jv = (k == 0) ? j0 : (k == 1) ? j1 : (k == 2) ? j2 : j3;
            jv = __shfl_sync(0xffffffffu, jv, src);
            if (lane == 0) lyp[u] = jv - logZ;
        }
    }
}

// ---------------- RNN-T alpha recursion: 1 warp per batch, 4 elems/lane ----------------
__device__ __forceinline__ float lsef(float a, float b)
{
    float mx = fmaxf(a, b), mn = fminf(a, b);
    return mx + __logf(1.f + __expf(mn - mx));
}

__global__ void __launch_bounds__(32) alpha_kernel(const int* __restrict__ xlen,
                                                   const int* __restrict__ ylen)
{
    const float BIG = -1e30f;
    int b = blockIdx.x;
    int lane = threadIdx.x;
    int tl = xlen[b], ul = ylen[b];
    const float* lbB = g_lb + (size_t)b * Tq * UP1;
    const float* lyB = g_ly + (size_t)b * Tq * Uq;
    int idx0 = lane * 4;

    float a[4];
    // row 0: alpha0[idx] = sum_{k<idx} ly[0][k]
    {
        float e[4];
#pragma unroll
        for (int j = 0; j < 4; j++) {
            int idx = idx0 + j;
            e[j] = (idx >= 1 && idx <= Uq) ? lyB[idx - 1] : 0.f;
        }
        float s[4];
        s[0] = e[0]; s[1] = s[0] + e[1]; s[2] = s[1] + e[2]; s[3] = s[2] + e[3];
        float v = s[3];
#pragma unroll
        for (int d = 1; d < 32; d <<= 1) {
            float t2 = __shfl_up_sync(0xffffffffu, v, d);
            if (lane >= d) v += t2;
        }
        float base = v - s[3];
#pragma unroll
        for (int j = 0; j < 4; j++) a[j] = base + s[j];
    }

    for (int t = 1; t < tl; t++) {
        const float* lyr = lyB + (size_t)t * Uq;
        const float* lbr = lbB + (size_t)(t - 1) * UP1;
        float e[4], lbv[4];
#pragma unroll
        for (int j = 0; j < 4; j++) {
            int idx = idx0 + j;
            e[j]   = (idx >= 1 && idx <= Uq) ? lyr[idx - 1] : 0.f;
            lbv[j] = (idx < UP1) ? lbr[idx] : 0.f;
        }
        float s[4];
        s[0] = e[0]; s[1] = s[0] + e[1]; s[2] = s[1] + e[2]; s[3] = s[2] + e[3];
        float v = s[3];
#pragma unroll
        for (int d = 1; d < 32; d <<= 1) {
            float t2 = __shfl_up_sync(0xffffffffu, v, d);
            if (lane >= d) v += t2;
        }
        float base = v - s[3];
        float cj[4];
#pragma unroll
        for (int j = 0; j < 4; j++) cj[j] = base + s[j];

        float x[4], m[4];
#pragma unroll
        for (int j = 0; j < 4; j++) {
            int idx = idx0 + j;
            x[j] = (idx < UP1) ? (a[j] + lbv[j] - cj[j]) : BIG;
        }
        m[0] = x[0];
        m[1] = lsef(m[0], x[1]);
        m[2] = lsef(m[1], x[2]);
        m[3] = lsef(m[2], x[3]);
        float z = m[3];
#pragma unroll
        for (int d = 1; d < 32; d <<= 1) {
            float t2 = __shfl_up_sync(0xffffffffu, z, d);
            if (lane >= d) z = lsef(z, t2);
        }
        float excl = __shfl_up_sync(0xffffffffu, z, 1);
        if (lane == 0) excl = BIG;
#pragma unroll
        for (int j = 0; j < 4; j++) a[j] = cj[j] + lsef(excl, m[j]);
    }

    float sel = a[ul & 3];
    float aul = __shfl_sync(0xffffffffu, sel, ul >> 2);
    if (lane == 0)
        g_nll[b] = -(aul + lbB[(size_t)(tl - 1) * UP1 + ul]);
}

__global__ void mean_kernel(float* __restrict__ out)
{
    float s = 0.f;
    for (int b = 0; b < Bq; b++) s += g_nll[b];
    out[0] = s / (float)Bq;
}

// ---------------- launch ----------------
extern "C" void kernel_launch(void* const* d_in, const int* in_sizes, int n_in,
                              void* d_out, int out_size)
{
    const float* xs    = (const float*)d_in[0];
    const int*   ys    = (const int*)  d_in[1];
    const int*   xlen  = (const int*)  d_in[2];
    const int*   ylen  = (const int*)  d_in[3];
    const float* eWih0 = (const float*)d_in[4];
    const float* eWhh0 = (const float*)d_in[5];
    const float* ebih0 = (const float*)d_in[6];
    const float* ebhh0 = (const float*)d_in[7];
    const float* eWih1 = (const float*)d_in[8];
    const float* eWhh1 = (const float*)d_in[9];
    const float* ebih1 = (const float*)d_in[10];
    const float* ebhh1 = (const float*)d_in[11];
    const float* eWo   = (const float*)d_in[12];
    const float* ebo   = (const float*)d_in[13];
    /* d_in[14] = embed (one-hot; folded into xpd gather) */
    const float* dWih  = (const float*)d_in[15];
    const float* dWhh  = (const float*)d_in[16];
    const float* dbih  = (const float*)d_in[17];
    const float* dbhh  = (const float*)d_in[18];
    const float* dWo   = (const float*)d_in[19];
    const float* dbo   = (const float*)d_in[20];
    float* out = (float*)d_out;

    float *xp0, *h0, *xp1, *h1, *enc, *xpd, *hd, *dec;
    cudaGetSymbolAddress((void**)&xp0, g_xp0);
    cudaGetSymbolAddress((void**)&h0,  g_h0);
    cudaGetSymbolAddress((void**)&xp1, g_xp1);
    cudaGetSymbolAddress((void**)&h1,  g_h1);
    cudaGetSymbolAddress((void**)&enc, g_enc);
    cudaGetSymbolAddress((void**)&xpd, g_xpd);
    cudaGetSymbolAddress((void**)&hd,  g_hd);
    cudaGetSymbolAddress((void**)&dec, g_dec);

    const int MT = Bq * Tq;      // 4000
    const int MU = Bq * UP1;     // 968

    // inputs for both recurrences
    gemm_nt<<<dim3(G4 / GBN, (MT + GBM - 1) / GBM), 256>>>(
        xs, eWih0, ebih0, ebhh0, xp0, MT, G4, DIN);
    xpd_kernel<<<Bq * UP1, 256>>>(ys, dWih, dbih, dbhh);

    // fused: encoder layer 0 (clusters 0-7) + decoder (clusters 8-15)
    lstm_kernel<<<128, 320>>>(eWhh0, xp0, h0, Tq, dWhh, xpd, hd, UP1);

    // encoder layer 1
    gemm_nt<<<dim3(G4 / GBN, (MT + GBM - 1) / GBM), 256>>>(
        h0, eWih1, ebih1, ebhh1, xp1, MT, G4, Hq);
    // decoder output projection (independent of enc layer 1)
    gemm_nt<<<dim3(Vq / GBN, (MU + GBM - 1) / GBM), 256>>>(
        hd, dWo, dbo, nullptr, dec, MU, Vq, Hq);
    lstm_kernel<<<64, 320>>>(eWhh1, xp1, h1, Tq, dWhh, xpd, hd, UP1);

    // encoder output projection
    gemm_nt<<<dim3(Vq / GBN, (MT + GBM - 1) / GBM), 256>>>(
        h1, eWo, ebo, nullptr, enc, MT, Vq, Hq);

    joint_kernel<<<dim3(Tq / 4, Bq), 128>>>(ys);
    alpha_kernel<<<Bq, 32>>>(xlen, ylen);
    mean_kernel<<<1, 1>>>(out);
}

// round 5
// speedup vs baseline: 1.3036x; 1.0388x over previous
#include <cuda_runtime.h>
#include <math.h>
#include <stdint.h>

#define Bq   8
#define Tq   500
#define Uq   120
#define UP1  121
#define Vq   128
#define Hq   320
#define G4   1280
#define DIN  80
#define VM1  127

// ---------------- static device scratch ----------------
__device__ float g_xp0[Bq * Tq * G4];
__device__ float g_h0 [Bq * Tq * Hq];
__device__ float g_xp1[Bq * Tq * G4];
__device__ float g_h1 [Bq * Tq * Hq];
__device__ float g_enc[Bq * Tq * Vq];
__device__ float g_xpd[Bq * UP1 * G4];
__device__ float g_hd [Bq * UP1 * Hq];
__device__ float g_dec[Bq * UP1 * Vq];
__device__ float g_lb [Bq * Tq * UP1];
__device__ float g_ly [Bq * Tq * Uq];
__device__ float g_nll[Bq];

__device__ __forceinline__ float tanh_f(float x)
{
    float e = __expf(2.f * fabsf(x));
    float r = 1.f - 2.f / (e + 1.f);
    return copysignf(r, x);
}

// ---------------- tiled GEMM: C[M,N] = A[M,K] @ B[N,K]^T + b1 + b2 ----------------
#define GBM 128
#define GBN 64
#define GBK 16

__global__ void __launch_bounds__(256) gemm_nt(const float* __restrict__ A,
                                               const float* __restrict__ Bm,
                                               const float* __restrict__ b1,
                                               const float* __restrict__ b2,
                                               float* __restrict__ C,
                                               int M, int N, int K)
{
    __shared__ float As[GBK][GBM + 4];
    __shared__ float Bs[GBK][GBN + 4];
    int tid = threadIdx.x;
    int bm = blockIdx.y * GBM;
    int bn = blockIdx.x * GBN;
    int tx = tid & 15, ty = tid >> 4;

    float acc[8][4];
#pragma unroll
    for (int i = 0; i < 8; i++)
#pragma unroll
        for (int j = 0; j < 4; j++) acc[i][j] = 0.f;

    for (int k0 = 0; k0 < K; k0 += GBK) {
#pragma unroll
        for (int l = 0; l < 8; l++) {
            int idx = l * 256 + tid;
            int am = idx >> 4, ak = idx & 15;
            float v = 0.f;
            if (bm + am < M && k0 + ak < K) v = A[(size_t)(bm + am) * K + k0 + ak];
            As[ak][am] = v;
        }
#pragma unroll
        for (int l = 0; l < 4; l++) {
            int idx = l * 256 + tid;
            int bnn = idx >> 4, bk = idx & 15;
            float v = 0.f;
            if (bn + bnn < N && k0 + bk < K) v = Bm[(size_t)(bn + bnn) * K + k0 + bk];
            Bs[bk][bnn] = v;
        }
        __syncthreads();
#pragma unroll
        for (int k = 0; k < GBK; k++) {
            float4 a0 = *(const float4*)&As[k][ty * 8];
            float4 a1 = *(const float4*)&As[k][ty * 8 + 4];
            float4 bv = *(const float4*)&Bs[k][tx * 4];
            float af[8] = {a0.x, a0.y, a0.z, a0.w, a1.x, a1.y, a1.z, a1.w};
            float bf[4] = {bv.x, bv.y, bv.z, bv.w};
#pragma unroll
            for (int i = 0; i < 8; i++)
#pragma unroll
                for (int j = 0; j < 4; j++) acc[i][j] += af[i] * bf[j];
        }
        __syncthreads();
    }

    int n0 = bn + tx * 4;
    float bias[4];
#pragma unroll
    for (int j = 0; j < 4; j++)
        bias[j] = (b1 ? b1[n0 + j] : 0.f) + (b2 ? b2[n0 + j] : 0.f);

#pragma unroll
    for (int i = 0; i < 8; i++) {
        int m = bm + ty * 8 + i;
        if (m >= M) continue;
        float4 r;
        r.x = acc[i][0] + bias[0];
        r.y = acc[i][1] + bias[1];
        r.z = acc[i][2] + bias[2];
        r.w = acc[i][3] + bias[3];
        *(float4*)&C[(size_t)m * N + n0] = r;
    }
}

// ---------------- LSTM: 8-CTA cluster/batch, st.async h-broadcast + mbarrier sync -------
// Double-buffered hbuf; each step's h broadcast via st.async carrying complete_tx to the
// peer's mbarrier (no barrier.cluster in the loop -> no per-step L1D flush, ~60-150cyc wait).
__global__ void __cluster_dims__(8, 1, 1) __launch_bounds__(320, 1)
lstm_kernel(const float* __restrict__ Whh_e, const float* __restrict__ xp_e,
            float* __restrict__ ho_e, int T_e,
            const float* __restrict__ Whh_d, const float* __restrict__ xp_d,
            float* __restrict__ ho_d, int T_d)
{
    __shared__ __align__(16) float hbuf[2][Hq];          // hbuf[1] = hbuf[0] + 1280B
    __shared__ __align__(8) unsigned long long mbars[2]; // mbars[1] = mbars[0] + 8B

    unsigned rank;
    asm("mov.u32 %0, %%cluster_ctarank;" : "=r"(rank));
    int cl = blockIdx.x >> 3;
    int is_dec = (cl >= Bq);
    int batch = cl & 7;
    const float* Whh   = is_dec ? Whh_d : Whh_e;
    const float* xproj = is_dec ? xp_d  : xp_e;
    float*       hout  = is_dec ? ho_d  : ho_e;
    int          T     = is_dec ? T_d   : T_e;

    int tid  = threadIdx.x;
    int half = tid & 1;           // K-half
    int lr   = tid >> 1;          // gate row 0..159
    int gate = lr & 3;            // i,f,g,o
    int unit = (int)rank * 40 + (lr >> 2);
    int row  = gate * Hq + unit;

    // register-resident weights: 160 floats as 40x ulonglong2 (f32x2 pairs)
    ulonglong2 wv[40];
    const ulonglong2* Wp =
        reinterpret_cast<const ulonglong2*>(Whh + (size_t)row * Hq + half * 160);
#pragma unroll
    for (int i = 0; i < 40; i++) wv[i] = Wp[i];

    hbuf[0][tid] = 0.f;
    float c = 0.f;

    unsigned mb_local = (unsigned)__cvta_generic_to_shared(&mbars[0]);
    if (tid == 0) {
        asm volatile("mbarrier.init.shared.b64 [%0], 1;" :: "r"(mb_local) : "memory");
        asm volatile("mbarrier.init.shared.b64 [%0], 1;" :: "r"(mb_local + 8) : "memory");
    }

    const float* xp = xproj + ((size_t)batch * T) * G4 + row;
    float xg_next = (half == 0) ? __ldg(xp) : 0.f;

    int lane  = tid & 31;
    int owner = ((tid & 7) == 0);

    // per-peer remote base addresses (buffer 0 slot + mbar 0); buffer 1 = +1280B / +8B
    unsigned h_local = (unsigned)__cvta_generic_to_shared(&hbuf[0][unit]);
    unsigned rh[8], rm[8];
#pragma unroll
    for (int r = 0; r < 8; r++) {
        asm("mapa.shared::cluster.u32 %0, %1, %2;" : "=r"(rh[r]) : "r"(h_local), "r"(r));
        asm("mapa.shared::cluster.u32 %0, %1, %2;" : "=r"(rm[r]) : "r"(mb_local), "r"(r));
    }

    __syncthreads();
    asm volatile("barrier.cluster.arrive.aligned;" ::: "memory");
    asm volatile("barrier.cluster.wait.aligned;" ::: "memory");

    unsigned ph0 = 0, ph1 = 0;   // phase parity per buffer-barrier

    for (int t = 0; t < T; t++) {
        int cur = t & 1, nxt = cur ^ 1;
        int not_last = (t + 1 < T);

        // arm the barrier that will collect this step's h broadcast (8 CTAs * 40 * 4B)
        if (not_last && tid == 0)
            asm volatile("mbarrier.arrive.expect_tx.shared.b64 _, [%0], 1280;"
                         :: "r"(mb_local + (unsigned)nxt * 8) : "memory");

        float xg = xg_next;
        if (half == 0 && not_last) xg_next = __ldg(xp + (size_t)(t + 1) * G4);

        const ulonglong2* h2 =
            reinterpret_cast<const ulonglong2*>(&hbuf[cur][half * 160]);
        unsigned long long acc0 = 0ULL, acc1 = 0ULL;
#pragma unroll
        for (int i = 0; i < 40; i++) {
            ulonglong2 hv = h2[i];
            asm("fma.rn.f32x2 %0, %1, %2, %0;" : "+l"(acc0) : "l"(wv[i].x), "l"(hv.x));
            asm("fma.rn.f32x2 %0, %1, %2, %0;" : "+l"(acc1) : "l"(wv[i].y), "l"(hv.y));
        }
        unsigned lo0, hi0, lo1, hi1;
        asm("mov.b64 {%0,%1}, %2;" : "=r"(lo0), "=r"(hi0) : "l"(acc0));
        asm("mov.b64 {%0,%1}, %2;" : "=r"(lo1), "=r"(hi1) : "l"(acc1));
        float a = (__uint_as_float(lo0) + __uint_as_float(hi0))
                + (__uint_as_float(lo1) + __uint_as_float(hi1));
        a += __shfl_xor_sync(0xffffffffu, a, 1);   // combine K-halves
        float g = a + xg;                          // valid on even lanes

        float xs = (gate == 2) ? (g + g) : g;
        float s  = 1.f / (1.f + __expf(-xs));
        float act = (gate == 2) ? (s + s - 1.f) : s;

        int base = lane & ~7;
        float vi = __shfl_sync(0xffffffffu, act, base + 0);
        float vf = __shfl_sync(0xffffffffu, act, base + 2);
        float vg = __shfl_sync(0xffffffffu, act, base + 4);
        float vo = __shfl_sync(0xffffffffu, act, base + 6);

        if (owner) {
            c = vf * c + vi * vg;
            float h = vo * tanh_f(c);
            hout[((size_t)batch * T + t) * Hq + unit] = h;
            if (not_last) {
                unsigned hbits = __float_as_uint(h);
                unsigned doff = (unsigned)nxt * (Hq * 4);
                unsigned moff = (unsigned)nxt * 8;
#pragma unroll
                for (int r = 0; r < 8; r++) {
                    asm volatile(
                        "st.async.shared::cluster.mbarrier::complete_tx::bytes.b32 "
                        "[%0], %1, [%2];"
                        :: "r"(rh[r] + doff), "r"(hbits), "r"(rm[r] + moff) : "memory");
                }
            }
        }

        if (not_last) {
            unsigned par = nxt ? ph1 : ph0;
            unsigned mb  = mb_local + (unsigned)nxt * 8;
            asm volatile(
                "{\n\t.reg .pred P;\n\t"
                "WL_%=:\n\t"
                "mbarrier.try_wait.parity.acquire.cta.shared::cta.b64 P, [%0], %1, 0x989680;\n\t"
                "@!P bra WL_%=;\n\t}"
                :: "r"(mb), "r"(par) : "memory");
            if (nxt) ph1 ^= 1; else ph0 ^= 1;
        }
    }
}

// ---------------- decoder xproj via embedding gather (one-hot rows) ----------------
__global__ void __launch_bounds__(256) xpd_kernel(const int* __restrict__ ys,
                                                  const float* __restrict__ Wih,
                                                  const float* __restrict__ bih,
                                                  const float* __restrict__ bhh)
{
    int b = blockIdx.x / UP1, u = blockIdx.x % UP1;
    int id = (u == 0) ? 0 : ys[b * Uq + u - 1];
    float* dst = g_xpd + ((size_t)b * UP1 + u) * G4;
    for (int g = threadIdx.x; g < G4; g += 256) {
        float v = bih[g] + bhh[g];
        if (id > 0) v += Wih[(size_t)g * VM1 + (id - 1)];
        dst[g] = v;
    }
}

// ---------------- joint + log-softmax -> lb (blank) and ly (label) only ----------------
__global__ void __launch_bounds__(128) joint_kernel(const int* __restrict__ ys)
{
    int b = blockIdx.y;
    int t = blockIdx.x * 4 + (threadIdx.x >> 5);
    int lane = threadIdx.x & 31;

    const float* e = g_enc + ((size_t)b * Tq + t) * Vq;
    float e0 = e[lane], e1 = e[32 + lane], e2 = e[64 + lane], e3 = e[96 + lane];
    float* lbp = g_lb + ((size_t)b * Tq + t) * UP1;
    float* lyp = g_ly + ((size_t)b * Tq + t) * Uq;

    for (int u = 0; u < UP1; u++) {
        const float* d = g_dec + ((size_t)b * UP1 + u) * Vq;
        float j0 = e0 + d[lane];
        float j1 = e1 + d[32 + lane];
        float j2 = e2 + d[64 + lane];
        float j3 = e3 + d[96 + lane];

        float m = fmaxf(fmaxf(j0, j1), fmaxf(j2, j3));
#pragma unroll
        for (int dlt = 16; dlt > 0; dlt >>= 1)
            m = fmaxf(m, __shfl_xor_sync(0xffffffffu, m, dlt));
        float s = __expf(j0 - m) + __expf(j1 - m) + __expf(j2 - m) + __expf(j3 - m);
#pragma unroll
        for (int dlt = 16; dlt > 0; dlt >>= 1)
            s += __shfl_xor_sync(0xffffffffu, s, dlt);
        float logZ = m + __logf(s);

        if (lane == 0) lbp[u] = j0 - logZ;
        if (u < Uq) {
            int lbl = ys[b * Uq + u];
            int k = lbl >> 5, src = lbl & 31;
            float jv = (k == 0) ? j0 : (k == 1) ? j1 : (k == 2) ? j2 : j3;
            jv = __shfl_sync(0xffffffffu, jv, src);
            if (lane == 0) lyp[u] = jv - logZ;
        }
    }
}

// ---------------- RNN-T alpha recursion: 1 warp/batch, 4 elems/lane, pipelined loads ----
__device__ __forceinline__ float lsef(float a, float b)
{
    float mx = fmaxf(a, b), mn = fminf(a, b);
    return mx + __logf(1.f + __expf(mn - mx));
}

__global__ void __launch_bounds__(32) alpha_kernel(const int* __restrict__ xlen,
                                                   const int* __restrict__ ylen)
{
    const float BIG = -1e30f;
    int b = blockIdx.x;
    int lane = threadIdx.x;
    int tl = xlen[b], ul = ylen[b];
    const float* lbB = g_lb + (size_t)b * Tq * UP1;
    const float* lyB = g_ly + (size_t)b * Tq * Uq;
    int idx0 = lane * 4;

    float a[4];
    {   // row 0: exclusive cumsum of ly[0]
        float e[4];
#pragma unroll
        for (int j = 0; j < 4; j++) {
            int idx = idx0 + j;
            e[j] = (idx >= 1 && idx <= Uq) ? __ldg(&lyB[idx - 1]) : 0.f;
        }
        float s[4];
        s[0] = e[0]; s[1] = s[0] + e[1]; s[2] = s[1] + e[2]; s[3] = s[2] + e[3];
        float v = s[3];
#pragma unroll
        for (int d = 1; d < 32; d <<= 1) {
            float t2 = __shfl_up_sync(0xffffffffu, v, d);
            if (lane >= d) v += t2;
        }
        float base = v - s[3];
#pragma unroll
        for (int j = 0; j < 4; j++) a[j] = base + s[j];
    }

    // software-pipelined row loads (lb/ly rows live in L2; hide ~250cyc)
    float e[4], lbv[4];
    {
        const float* lyr = lyB + (size_t)1 * Uq;
        const float* lbr = lbB;
#pragma unroll
        for (int j = 0; j < 4; j++) {
            int idx = idx0 + j;
            e[j]   = (idx >= 1 && idx <= Uq) ? __ldg(&lyr[idx - 1]) : 0.f;
            lbv[j] = (idx < UP1) ? __ldg(&lbr[idx]) : 0.f;
        }
    }

    for (int t = 1; t < tl; t++) {
        float en[4], lbn[4];
        if (t + 1 < tl) {
            const float* lyr2 = lyB + (size_t)(t + 1) * Uq;
            const float* lbr2 = lbB + (size_t)t * UP1;
#pragma unroll
            for (int j = 0; j < 4; j++) {
                int idx = idx0 + j;
                en[j]  = (idx >= 1 && idx <= Uq) ? __ldg(&lyr2[idx - 1]) : 0.f;
                lbn[j] = (idx < UP1) ? __ldg(&lbr2[idx]) : 0.f;
            }
        }

        float s[4];
        s[0] = e[0]; s[1] = s[0] + e[1]; s[2] = s[1] + e[2]; s[3] = s[2] + e[3];
        float v = s[3];
#pragma unroll
        for (int d = 1; d < 32; d <<= 1) {
            float t2 = __shfl_up_sync(0xffffffffu, v, d);
            if (lane >= d) v += t2;
        }
        float base = v - s[3];
        float cj[4];
#pragma unroll
        for (int j = 0; j < 4; j++) cj[j] = base + s[j];

        float x[4], m[4];
#pragma unroll
        for (int j = 0; j < 4; j++) {
            int idx = idx0 + j;
            x[j] = (idx < UP1) ? (a[j] + lbv[j] - cj[j]) : BIG;
        }
        m[0] = x[0];
        m[1] = lsef(m[0], x[1]);
        m[2] = lsef(m[1], x[2]);
        m[3] = lsef(m[2], x[3]);
        float z = m[3];
#pragma unroll
        for (int d = 1; d < 32; d <<= 1) {
            float t2 = __shfl_up_sync(0xffffffffu, z, d);
            if (lane >= d) z = lsef(z, t2);
        }
        float excl = __shfl_up_sync(0xffffffffu, z, 1);
        if (lane == 0) excl = BIG;
#pragma unroll
        for (int j = 0; j < 4; j++) a[j] = cj[j] + lsef(excl, m[j]);

#pragma unroll
        for (int j = 0; j < 4; j++) { e[j] = en[j]; lbv[j] = lbn[j]; }
    }

    float sel = a[ul & 3];
    float aul = __shfl_sync(0xffffffffu, sel, ul >> 2);
    if (lane == 0)
        g_nll[b] = -(aul + __ldg(&lbB[(size_t)(tl - 1) * UP1 + ul]));
}

__global__ void mean_kernel(float* __restrict__ out)
{
    float s = 0.f;
    for (int b = 0; b < Bq; b++) s += g_nll[b];
    out[0] = s / (float)Bq;
}

// ---------------- launch ----------------
extern "C" void kernel_launch(void* const* d_in, const int* in_sizes, int n_in,
                              void* d_out, int out_size)
{
    const float* xs    = (const float*)d_in[0];
    const int*   ys    = (const int*)  d_in[1];
    const int*   xlen  = (const int*)  d_in[2];
    const int*   ylen  = (const int*)  d_in[3];
    const float* eWih0 = (const float*)d_in[4];
    const float* eWhh0 = (const float*)d_in[5];
    const float* ebih0 = (const float*)d_in[6];
    const float* ebhh0 = (const float*)d_in[7];
    const float* eWih1 = (const float*)d_in[8];
    const float* eWhh1 = (const float*)d_in[9];
    const float* ebih1 = (const float*)d_in[10];
    const float* ebhh1 = (const float*)d_in[11];
    const float* eWo   = (const float*)d_in[12];
    const float* ebo   = (const float*)d_in[13];
    /* d_in[14] = embed (one-hot; folded into xpd gather) */
    const float* dWih  = (const float*)d_in[15];
    const float* dWhh  = (const float*)d_in[16];
    const float* dbih  = (const float*)d_in[17];
    const float* dbhh  = (const float*)d_in[18];
    const float* dWo   = (const float*)d_in[19];
    const float* dbo   = (const float*)d_in[20];
    float* out = (float*)d_out;

    float *xp0, *h0, *xp1, *h1, *enc, *xpd, *hd, *dec;
    cudaGetSymbolAddress((void**)&xp0, g_xp0);
    cudaGetSymbolAddress((void**)&h0,  g_h0);
    cudaGetSymbolAddress((void**)&xp1, g_xp1);
    cudaGetSymbolAddress((void**)&h1,  g_h1);
    cudaGetSymbolAddress((void**)&enc, g_enc);
    cudaGetSymbolAddress((void**)&xpd, g_xpd);
    cudaGetSymbolAddress((void**)&hd,  g_hd);
    cudaGetSymbolAddress((void**)&dec, g_dec);

    const int MT = Bq * Tq;      // 4000
    const int MU = Bq * UP1;     // 968

    gemm_nt<<<dim3(G4 / GBN, (MT + GBM - 1) / GBM), 256>>>(
        xs, eWih0, ebih0, ebhh0, xp0, MT, G4, DIN);
    xpd_kernel<<<Bq * UP1, 256>>>(ys, dWih, dbih, dbhh);

    // fused: encoder layer 0 (clusters 0-7) + decoder (clusters 8-15)
    lstm_kernel<<<128, 320>>>(eWhh0, xp0, h0, Tq, dWhh, xpd, hd, UP1);

    gemm_nt<<<dim3(G4 / GBN, (MT + GBM - 1) / GBM), 256>>>(
        h0, eWih1, ebih1, ebhh1, xp1, MT, G4, Hq);
    gemm_nt<<<dim3(Vq / GBN, (MU + GBM - 1) / GBM), 256>>>(
        hd, dWo, dbo, nullptr, dec, MU, Vq, Hq);
    lstm_kernel<<<64, 320>>>(eWhh1, xp1, h1, Tq, dWhh, xpd, hd, UP1);

    gemm_nt<<<dim3(Vq / GBN, (MT + GBM - 1) / GBM), 256>>>(
        h1, eWo, ebo, nullptr, enc, MT, Vq, Hq);

    joint_kernel<<<dim3(Tq / 4, Bq), 128>>>(ys);
    alpha_kernel<<<Bq, 32>>>(xlen, ylen);
    mean_kernel<<<1, 1>>>(out);
}

// round 6
// speedup vs baseline: 1.3836x; 1.0613x over previous
#include <cuda_runtime.h>
#include <math.h>
#include <stdint.h>

#define Bq   8
#define Tq   500
#define Uq   120
#define UP1  121
#define Vq   128
#define Hq   320
#define G4   1280
#define DIN  80
#define VM1  127

// ---------------- static device scratch ----------------
__device__ float g_xp0[Bq * Tq * G4];
__device__ float g_h0 [Bq * Tq * Hq];
__device__ float g_xp1[Bq * Tq * G4];
__device__ float g_h1 [Bq * Tq * Hq];
__device__ float g_enc[Bq * Tq * Vq];
__device__ float g_xpd[Bq * UP1 * G4];
__device__ float g_hd [Bq * UP1 * Hq];
__device__ float g_dec[Bq * UP1 * Vq];
__device__ float g_lb [Bq * Tq * UP1];
__device__ float g_ly [Bq * Tq * Uq];
__device__ float g_nll[Bq];

__device__ __forceinline__ float sig_f(float x)
{
    return __fdividef(1.f, 1.f + __expf(-x));
}
__device__ __forceinline__ float tanh_f(float x)
{
    float e = __expf(2.f * fabsf(x));
    float r = 1.f - __fdividef(2.f, e + 1.f);
    return copysignf(r, x);
}

// ---------------- tiled GEMM: C[M,N] = A[M,K] @ B[N,K]^T + b1 + b2 ----------------
#define GBM 128
#define GBN 64
#define GBK 16

__global__ void __launch_bounds__(256) gemm_nt(const float* __restrict__ A,
                                               const float* __restrict__ Bm,
                                               const float* __restrict__ b1,
                                               const float* __restrict__ b2,
                                               float* __restrict__ C,
                                               int M, int N, int K)
{
    __shared__ float As[GBK][GBM + 4];
    __shared__ float Bs[GBK][GBN + 4];
    int tid = threadIdx.x;
    int bm = blockIdx.y * GBM;
    int bn = blockIdx.x * GBN;
    int tx = tid & 15, ty = tid >> 4;

    float acc[8][4];
#pragma unroll
    for (int i = 0; i < 8; i++)
#pragma unroll
        for (int j = 0; j < 4; j++) acc[i][j] = 0.f;

    for (int k0 = 0; k0 < K; k0 += GBK) {
#pragma unroll
        for (int l = 0; l < 8; l++) {
            int idx = l * 256 + tid;
            int am = idx >> 4, ak = idx & 15;
            float v = 0.f;
            if (bm + am < M && k0 + ak < K) v = A[(size_t)(bm + am) * K + k0 + ak];
            As[ak][am] = v;
        }
#pragma unroll
        for (int l = 0; l < 4; l++) {
            int idx = l * 256 + tid;
            int bnn = idx >> 4, bk = idx & 15;
            float v = 0.f;
            if (bn + bnn < N && k0 + bk < K) v = Bm[(size_t)(bn + bnn) * K + k0 + bk];
            Bs[bk][bnn] = v;
        }
        __syncthreads();
#pragma unroll
        for (int k = 0; k < GBK; k++) {
            float4 a0 = *(const float4*)&As[k][ty * 8];
            float4 a1 = *(const float4*)&As[k][ty * 8 + 4];
            float4 bv = *(const float4*)&Bs[k][tx * 4];
            float af[8] = {a0.x, a0.y, a0.z, a0.w, a1.x, a1.y, a1.z, a1.w};
            float bf[4] = {bv.x, bv.y, bv.z, bv.w};
#pragma unroll
            for (int i = 0; i < 8; i++)
#pragma unroll
                for (int j = 0; j < 4; j++) acc[i][j] += af[i] * bf[j];
        }
        __syncthreads();
    }

    int n0 = bn + tx * 4;
    float bias[4];
#pragma unroll
    for (int j = 0; j < 4; j++)
        bias[j] = (b1 ? b1[n0 + j] : 0.f) + (b2 ? b2[n0 + j] : 0.f);

#pragma unroll
    for (int i = 0; i < 8; i++) {
        int m = bm + ty * 8 + i;
        if (m >= M) continue;
        float4 r;
        r.x = acc[i][0] + bias[0];
        r.y = acc[i][1] + bias[1];
        r.z = acc[i][2] + bias[2];
        r.w = acc[i][3] + bias[3];
        *(float4*)&C[(size_t)m * N + n0] = r;
    }
}

// ---------------- LSTM: 8-CTA cluster/batch; thread = (unit, K-slice) --------------------
// s = tid&7 K-slice (40 wide), rg = tid>>3 unit. Thread computes all 4 gates of its unit
// over its slice (160 MACs from 40 h loads -> 4x fewer LDS, warp has only 8 distinct
// addresses -> broadcast). 3-step shfl butterfly combines slices; all 8 lanes then hold
// identical gates -> redundant activations, no gathers. Sync: st.async + mbarrier.
__global__ void __cluster_dims__(8, 1, 1) __launch_bounds__(320, 1)
lstm_kernel(const float* __restrict__ Whh_e, const float* __restrict__ xp_e,
            float* __restrict__ ho_e, int T_e,
            const float* __restrict__ Whh_d, const float* __restrict__ xp_d,
            float* __restrict__ ho_d, int T_d)
{
    __shared__ __align__(16) float hbuf[2][Hq];          // buffer stride 1280 B
    __shared__ __align__(8) unsigned long long mbars[2];

    unsigned rank;
    asm("mov.u32 %0, %%cluster_ctarank;" : "=r"(rank));
    int cl = blockIdx.x >> 3;
    int is_dec = (cl >= Bq);
    int batch = cl & 7;
    const float* Whh   = is_dec ? Whh_d : Whh_e;
    const float* xproj = is_dec ? xp_d  : xp_e;
    float*       hout  = is_dec ? ho_d  : ho_e;
    int          T     = is_dec ? T_d   : T_e;

    int tid = threadIdx.x;
    int s   = tid & 7;            // K-slice
    int rg  = tid >> 3;           // local unit 0..39
    int unit = (int)rank * 40 + rg;

    // register-resident weights: 4 gates x 40 K = 160 floats as 80 u64 (K-paired)
    unsigned long long w[4][20];
#pragma unroll
    for (int r = 0; r < 4; r++) {
        const ulonglong2* p = reinterpret_cast<const ulonglong2*>(
            Whh + (size_t)(r * Hq + unit) * Hq + s * 40);
#pragma unroll
        for (int i = 0; i < 10; i++) {
            ulonglong2 u = p[i];
            w[r][2 * i] = u.x; w[r][2 * i + 1] = u.y;
        }
    }

    hbuf[0][tid] = 0.f;
    float c = 0.f;

    unsigned mb_local = (unsigned)__cvta_generic_to_shared(&mbars[0]);
    if (tid == 0) {
        asm volatile("mbarrier.init.shared.b64 [%0], 1;" :: "r"(mb_local) : "memory");
        asm volatile("mbarrier.init.shared.b64 [%0], 1;" :: "r"(mb_local + 8) : "memory");
    }

    const float* xpb = xproj + ((size_t)batch * T) * G4 + unit;
    float xg0 = 0.f, xg1 = 0.f, xg2 = 0.f, xg3 = 0.f;
    if (s == 0) {
        xg0 = __ldg(xpb);
        xg1 = __ldg(xpb + Hq);
        xg2 = __ldg(xpb + 2 * Hq);
        xg3 = __ldg(xpb + 3 * Hq);
    }

    unsigned h_local = (unsigned)__cvta_generic_to_shared(&hbuf[0][unit]);

    __syncthreads();
    asm volatile("barrier.cluster.arrive.aligned;" ::: "memory");
    asm volatile("barrier.cluster.wait.aligned;" ::: "memory");

    unsigned ph0 = 0, ph1 = 0;

    for (int t = 0; t < T; t++) {
        int cur = t & 1, nxt = cur ^ 1;
        int not_last = (t + 1 < T);

        if (not_last && tid == 0)
            asm volatile("mbarrier.arrive.expect_tx.shared.b64 _, [%0], 1280;"
                         :: "r"(mb_local + (unsigned)nxt * 8) : "memory");

        // matvec: 4 gate rows x 40 K, f32x2 packed
        const ulonglong2* h2 =
            reinterpret_cast<const ulonglong2*>(&hbuf[cur][s * 40]);
        unsigned long long a0 = 0ULL, a1 = 0ULL, a2 = 0ULL, a3 = 0ULL;
#pragma unroll
        for (int i = 0; i < 10; i++) {
            ulonglong2 hv = h2[i];
            asm("fma.rn.f32x2 %0, %1, %2, %0;" : "+l"(a0) : "l"(w[0][2*i]),   "l"(hv.x));
            asm("fma.rn.f32x2 %0, %1, %2, %0;" : "+l"(a1) : "l"(w[1][2*i]),   "l"(hv.x));
            asm("fma.rn.f32x2 %0, %1, %2, %0;" : "+l"(a2) : "l"(w[2][2*i]),   "l"(hv.x));
            asm("fma.rn.f32x2 %0, %1, %2, %0;" : "+l"(a3) : "l"(w[3][2*i]),   "l"(hv.x));
            asm("fma.rn.f32x2 %0, %1, %2, %0;" : "+l"(a0) : "l"(w[0][2*i+1]), "l"(hv.y));
            asm("fma.rn.f32x2 %0, %1, %2, %0;" : "+l"(a1) : "l"(w[1][2*i+1]), "l"(hv.y));
            asm("fma.rn.f32x2 %0, %1, %2, %0;" : "+l"(a2) : "l"(w[2][2*i+1]), "l"(hv.y));
            asm("fma.rn.f32x2 %0, %1, %2, %0;" : "+l"(a3) : "l"(w[3][2*i+1]), "l"(hv.y));
        }
        float g0, g1, g2, g3;
        {
            unsigned lo, hi;
            asm("mov.b64 {%0,%1}, %2;" : "=r"(lo), "=r"(hi) : "l"(a0));
            g0 = __uint_as_float(lo) + __uint_as_float(hi);
            asm("mov.b64 {%0,%1}, %2;" : "=r"(lo), "=r"(hi) : "l"(a1));
            g1 = __uint_as_float(lo) + __uint_as_float(hi);
            asm("mov.b64 {%0,%1}, %2;" : "=r"(lo), "=r"(hi) : "l"(a2));
            g2 = __uint_as_float(lo) + __uint_as_float(hi);
            asm("mov.b64 {%0,%1}, %2;" : "=r"(lo), "=r"(hi) : "l"(a3));
            g3 = __uint_as_float(lo) + __uint_as_float(hi);
        }
        if (s == 0) { g0 += xg0; g1 += xg1; g2 += xg2; g3 += xg3; }

        // prefetch next-step xproj (hidden behind butterfly + tail + wait)
        if (s == 0 && not_last) {
            const float* xq = xpb + (size_t)(t + 1) * G4;
            xg0 = __ldg(xq);
            xg1 = __ldg(xq + Hq);
            xg2 = __ldg(xq + 2 * Hq);
            xg3 = __ldg(xq + 3 * Hq);
        }

        // butterfly sum over the 8 slice lanes
#pragma unroll
        for (int d = 1; d < 8; d <<= 1) {
            g0 += __shfl_xor_sync(0xffffffffu, g0, d);
            g1 += __shfl_xor_sync(0xffffffffu, g1, d);
            g2 += __shfl_xor_sync(0xffffffffu, g2, d);
            g3 += __shfl_xor_sync(0xffffffffu, g3, d);
        }

        float i_ = sig_f(g0);
        float f_ = sig_f(g1);
        float gg = tanh_f(g2);
        float o_ = sig_f(g3);
        c = f_ * c + i_ * gg;
        float h = o_ * tanh_f(c);

        if (s == 0) {
            hout[((size_t)batch * T + t) * Hq + unit] = h;
            if (not_last) {
                unsigned hbits = __float_as_uint(h);
                unsigned doff = (unsigned)nxt * (Hq * 4);
                unsigned moff = (unsigned)nxt * 8;
#pragma unroll
                for (int r = 0; r < 8; r++) {
                    unsigned rh, rm;
                    asm("mapa.shared::cluster.u32 %0, %1, %2;"
                        : "=r"(rh) : "r"(h_local), "r"(r));
                    asm("mapa.shared::cluster.u32 %0, %1, %2;"
                        : "=r"(rm) : "r"(mb_local), "r"(r));
                    asm volatile(
                        "st.async.shared::cluster.mbarrier::complete_tx::bytes.b32 "
                        "[%0], %1, [%2];"
                        :: "r"(rh + doff), "r"(hbits), "r"(rm + moff) : "memory");
                }
            }
        }

        if (not_last) {
            unsigned par = nxt ? ph1 : ph0;
            unsigned mb  = mb_local + (unsigned)nxt * 8;
            asm volatile(
                "{\n\t.reg .pred P;\n\t"
                "WL_%=:\n\t"
                "mbarrier.try_wait.parity.acquire.cta.shared::cta.b64 P, [%0], %1, 0x989680;\n\t"
                "@!P bra WL_%=;\n\t}"
                :: "r"(mb), "r"(par) : "memory");
            if (nxt) ph1 ^= 1; else ph0 ^= 1;
        }
    }
}

// ---------------- decoder xproj via embedding gather (one-hot rows) ----------------
__global__ void __launch_bounds__(256) xpd_kernel(const int* __restrict__ ys,
                                                  const float* __restrict__ Wih,
                                                  const float* __restrict__ bih,
                                                  const float* __restrict__ bhh)
{
    int b = blockIdx.x / UP1, u = blockIdx.x % UP1;
    int id = (u == 0) ? 0 : ys[b * Uq + u - 1];
    float* dst = g_xpd + ((size_t)b * UP1 + u) * G4;
    for (int g = threadIdx.x; g < G4; g += 256) {
        float v = bih[g] + bhh[g];
        if (id > 0) v += Wih[(size_t)g * VM1 + (id - 1)];
        dst[g] = v;
    }
}

// ---------------- joint + log-softmax -> lb (blank) and ly (label) only ----------------
__global__ void __launch_bounds__(128) joint_kernel(const int* __restrict__ ys)
{
    int b = blockIdx.y;
    int t = blockIdx.x * 4 + (threadIdx.x >> 5);
    int lane = threadIdx.x & 31;

    const float* e = g_enc + ((size_t)b * Tq + t) * Vq;
    float e0 = e[lane], e1 = e[32 + lane], e2 = e[64 + lane], e3 = e[96 + lane];
    float* lbp = g_lb + ((size_t)b * Tq + t) * UP1;
    float* lyp = g_ly + ((size_t)b * Tq + t) * Uq;

    for (int u = 0; u < UP1; u++) {
        const float* d = g_dec + ((size_t)b * UP1 + u) * Vq;
        float j0 = e0 + d[lane];
        float j1 = e1 + d[32 + lane];
        float j2 = e2 + d[64 + lane];
        float j3 = e3 + d[96 + lane];

        float m = fmaxf(fmaxf(j0, j1), fmaxf(j2, j3));
#pragma unroll
        for (int dlt = 16; dlt > 0; dlt >>= 1)
            m = fmaxf(m, __shfl_xor_sync(0xffffffffu, m, dlt));
        float sm = __expf(j0 - m) + __expf(j1 - m) + __expf(j2 - m) + __expf(j3 - m);
#pragma unroll
        for (int dlt = 16; dlt > 0; dlt >>= 1)
            sm += __shfl_xor_sync(0xffffffffu, sm, dlt);
        float logZ = m + __logf(sm);

        if (lane == 0) lbp[u] = j0 - logZ;
        if (u < Uq) {
            int lbl = ys[b * Uq + u];
            int k = lbl >> 5, src = lbl & 31;
            float jv = (k == 0) ? j0 : (k == 1) ? j1 : (k == 2) ? j2 : j3;
            jv = __shfl_sync(0xffffffffu, jv, src);
            if (lane == 0) lyp[u] = jv - logZ;
        }
    }
}

// ---------------- RNN-T alpha recursion: 1 warp/batch, 4 elems/lane, pipelined loads ----
__device__ __forceinline__ float lsef(float a, float b)
{
    float mx = fmaxf(a, b), mn = fminf(a, b);
    return mx + __logf(1.f + __expf(mn - mx));
}

__global__ void __launch_bounds__(32) alpha_kernel(const int* __restrict__ xlen,
                                                   const int* __restrict__ ylen)
{
    const float BIG = -1e30f;
    int b = blockIdx.x;
    int lane = threadIdx.x;
    int tl = xlen[b], ul = ylen[b];
    const float* lbB = g_lb + (size_t)b * Tq * UP1;
    const float* lyB = g_ly + (size_t)b * Tq * Uq;
    int idx0 = lane * 4;

    float a[4];
    {   // row 0
        float e[4];
#pragma unroll
        for (int j = 0; j < 4; j++) {
            int idx = idx0 + j;
            e[j] = (idx >= 1 && idx <= Uq) ? __ldg(&lyB[idx - 1]) : 0.f;
        }
        float s[4];
        s[0] = e[0]; s[1] = s[0] + e[1]; s[2] = s[1] + e[2]; s[3] = s[2] + e[3];
        float v = s[3];
#pragma unroll
        for (int d = 1; d < 32; d <<= 1) {
            float t2 = __shfl_up_sync(0xffffffffu, v, d);
            if (lane >= d) v += t2;
        }
        float base = v - s[3];
#pragma unroll
        for (int j = 0; j < 4; j++) a[j] = base + s[j];
    }

    float e[4], lbv[4];
    {
        const float* lyr = lyB + (size_t)1 * Uq;
        const float* lbr = lbB;
#pragma unroll
        for (int j = 0; j < 4; j++) {
            int idx = idx0 + j;
            e[j]   = (idx >= 1 && idx <= Uq) ? __ldg(&lyr[idx - 1]) : 0.f;
            lbv[j] = (idx < UP1) ? __ldg(&lbr[idx]) : 0.f;
        }
    }

    for (int t = 1; t < tl; t++) {
        float en[4], lbn[4];
        if (t + 1 < tl) {
            const float* lyr2 = lyB + (size_t)(t + 1) * Uq;
            const float* lbr2 = lbB + (size_t)t * UP1;
#pragma unroll
            for (int j = 0; j < 4; j++) {
                int idx = idx0 + j;
                en[j]  = (idx >= 1 && idx <= Uq) ? __ldg(&lyr2[idx - 1]) : 0.f;
                lbn[j] = (idx < UP1) ? __ldg(&lbr2[idx]) : 0.f;
            }
        }

        float s[4];
        s[0] = e[0]; s[1] = s[0] + e[1]; s[2] = s[1] + e[2]; s[3] = s[2] + e[3];
        float v = s[3];
#pragma unroll
        for (int d = 1; d < 32; d <<= 1) {
            float t2 = __shfl_up_sync(0xffffffffu, v, d);
            if (lane >= d) v += t2;
        }
        float base = v - s[3];
        float cj[4];
#pragma unroll
        for (int j = 0; j < 4; j++) cj[j] = base + s[j];

        float x[4], m[4];
#pragma unroll
        for (int j = 0; j < 4; j++) {
            int idx = idx0 + j;
            x[j] = (idx < UP1) ? (a[j] + lbv[j] - cj[j]) : BIG;
        }
        m[0] = x[0];
        m[1] = lsef(m[0], x[1]);
        m[2] = lsef(m[1], x[2]);
        m[3] = lsef(m[2], x[3]);
        float z = m[3];
#pragma unroll
        for (int d = 1; d < 32; d <<= 1) {
            float t2 = __shfl_up_sync(0xffffffffu, z, d);
            if (lane >= d) z = lsef(z, t2);
        }
        float excl = __shfl_up_sync(0xffffffffu, z, 1);
        if (lane == 0) excl = BIG;
#pragma unroll
        for (int j = 0; j < 4; j++) a[j] = cj[j] + lsef(excl, m[j]);

#pragma unroll
        for (int j = 0; j < 4; j++) { e[j] = en[j]; lbv[j] = lbn[j]; }
    }

    float sel = a[ul & 3];
    float aul = __shfl_sync(0xffffffffu, sel, ul >> 2);
    if (lane == 0)
        g_nll[b] = -(aul + __ldg(&lbB[(size_t)(tl - 1) * UP1 + ul]));
}

__global__ void mean_kernel(float* __restrict__ out)
{
    float s = 0.f;
    for (int b = 0; b < Bq; b++) s += g_nll[b];
    out[0] = s / (float)Bq;
}

// ---------------- launch ----------------
extern "C" void kernel_launch(void* const* d_in, const int* in_sizes, int n_in,
                              void* d_out, int out_size)
{
    const float* xs    = (const float*)d_in[0];
    const int*   ys    = (const int*)  d_in[1];
    const int*   xlen  = (const int*)  d_in[2];
    const int*   ylen  = (const int*)  d_in[3];
    const float* eWih0 = (const float*)d_in[4];
    const float* eWhh0 = (const float*)d_in[5];
    const float* ebih0 = (const float*)d_in[6];
    const float* ebhh0 = (const float*)d_in[7];
    const float* eWih1 = (const float*)d_in[8];
    const float* eWhh1 = (const float*)d_in[9];
    const float* ebih1 = (const float*)d_in[10];
    const float* ebhh1 = (const float*)d_in[11];
    const float* eWo   = (const float*)d_in[12];
    const float* ebo   = (const float*)d_in[13];
    /* d_in[14] = embed (one-hot; folded into xpd gather) */
    const float* dWih  = (const float*)d_in[15];
    const float* dWhh  = (const float*)d_in[16];
    const float* dbih  = (const float*)d_in[17];
    const float* dbhh  = (const float*)d_in[18];
    const float* dWo   = (const float*)d_in[19];
    const float* dbo   = (const float*)d_in[20];
    float* out = (float*)d_out;

    float *xp0, *h0, *xp1, *h1, *enc, *xpd, *hd, *dec;
    cudaGetSymbolAddress((void**)&xp0, g_xp0);
    cudaGetSymbolAddress((void**)&h0,  g_h0);
    cudaGetSymbolAddress((void**)&xp1, g_xp1);
    cudaGetSymbolAddress((void**)&h1,  g_h1);
    cudaGetSymbolAddress((void**)&enc, g_enc);
    cudaGetSymbolAddress((void**)&xpd, g_xpd);
    cudaGetSymbolAddress((void**)&hd,  g_hd);
    cudaGetSymbolAddress((void**)&dec, g_dec);

    const int MT = Bq * Tq;      // 4000
    const int MU = Bq * UP1;     // 968

    gemm_nt<<<dim3(G4 / GBN, (MT + GBM - 1) / GBM), 256>>>(
        xs, eWih0, ebih0, ebhh0, xp0, MT, G4, DIN);
    xpd_kernel<<<Bq * UP1, 256>>>(ys, dWih, dbih, dbhh);

    // fused: encoder layer 0 (clusters 0-7) + decoder (clusters 8-15)
    lstm_kernel<<<128, 320>>>(eWhh0, xp0, h0, Tq, dWhh, xpd, hd, UP1);

    gemm_nt<<<dim3(G4 / GBN, (MT + GBM - 1) / GBM), 256>>>(
        h0, eWih1, ebih1, ebhh1, xp1, MT, G4, Hq);
    gemm_nt<<<dim3(Vq / GBN, (MU + GBM - 1) / GBM), 256>>>(
        hd, dWo, dbo, nullptr, dec, MU, Vq, Hq);
    lstm_kernel<<<64, 320>>>(eWhh1, xp1, h1, Tq, dWhh, xpd, hd, UP1);

    gemm_nt<<<dim3(Vq / GBN, (MT + GBM - 1) / GBM), 256>>>(
        h1, eWo, ebo, nullptr, enc, MT, Vq, Hq);

    joint_kernel<<<dim3(Tq / 4, Bq), 128>>>(ys);
    alpha_kernel<<<Bq, 32>>>(xlen, ylen);
    mean_kernel<<<1, 1>>>(out);
}